// round 8
// baseline (speedup 1.0000x reference)
#include <cuda_runtime.h>
#include <cstdint>

#define N_NODES   100000
#define N_EDGES   1600000
#define D         32
#define OUT_FEAT  32
#define CAP       96      // max edges/node bucket (Poisson mean 16; P(>=96) ~ 0)

// Device-global scratch (zero-init at load; g_cnt re-zeroed by K2 each call)
__device__ int g_cnt[N_NODES];
__device__ int g_bucket[(size_t)N_NODES * CAP];   // 38.4 MB edge-id buckets

#define TPB  128
#define NB   128
#define XSTR 33

#define E_PER_THREAD 4
#define PLACE_BLOCKS (N_EDGES / (TPB * E_PER_THREAD))   // 3125
#define F_BLOCKS     ((N_NODES + NB - 1) / NB)          // 782

// smem: xs[128][33] + w1[64][32] + w2[32][32] + gb[32] + b2[32]
#define SMEM_FLOATS (NB * XSTR + 64 * 32 + 32 * 32 + 32 + 32)

// ---------------------------------------------------------------------------
// Kernel 1: bucket edge ids by receiver. 1.6M atomic lanes (8x fewer than
// payload scatter; beats the 1.29 cyc/lane REDG-issue floor of red.v4).
// ---------------------------------------------------------------------------
__global__ __launch_bounds__(TPB) void place_kernel(
    const int* __restrict__ receivers)
{
    const int e0 = blockIdx.x * (TPB * E_PER_THREAD) + threadIdx.x;
    int r[E_PER_THREAD];
    #pragma unroll
    for (int t = 0; t < E_PER_THREAD; t++)
        r[t] = receivers[e0 + TPB * t];
    #pragma unroll
    for (int t = 0; t < E_PER_THREAD; t++) {
        int e = e0 + TPB * t;
        if ((unsigned)r[t] < N_NODES) {
            int pos = atomicAdd(&g_cnt[r[t]], 1);
            if (pos < CAP)
                g_bucket[(size_t)r[t] * CAP + pos] = e;
        }
    }
}

// ---------------------------------------------------------------------------
// Kernel 2: gather + FULL MLP per 128-node block.
//  phase 1: stage node_attr -> xs; acc = gb + node @ W1[0:32]
//  phase 2: warp-per-node gather (ids preloaded to regs, edge loads fully
//           independent & coalesced 4x128B/iter) -> agg into xs (overwrite)
//  phase 3: acc += agg @ W1[32:64]; relu; h @ W2 + b2 -> out
// Re-zeroes g_cnt. No g_agg / g_partial round-trips at all.
// ---------------------------------------------------------------------------
__global__ __launch_bounds__(TPB) void gather_mlp_kernel(
    const float* __restrict__ node_attr,
    const float* __restrict__ global_attr,
    const float* __restrict__ edge_attr,
    const float* __restrict__ W1, const float* __restrict__ b1,
    const float* __restrict__ W2, const float* __restrict__ b2,
    float* __restrict__ out)
{
    extern __shared__ float smem[];
    float* xs  = smem;                 // [NB][XSTR]: node attrs, then agg, then h
    float* w1s = xs + NB * XSTR;       // [64][32]
    float* w2s = w1s + 64 * 32;        // [32][32]
    float* gb  = w2s + 32 * 32;        // [32]
    float* b2s = gb + 32;              // [32]

    const int tid  = threadIdx.x;
    const int cg   = tid & 3;
    const int q    = tid >> 2;
    const int base = blockIdx.x * NB;
    const int nvalid = min(NB, N_NODES - base);
    const bool full  = (nvalid == NB);

    // ---- stage W1 (64 rows), W2; compute gb ----
    {
        const float4* w1v = reinterpret_cast<const float4*>(W1);
        const float4* w2v = reinterpret_cast<const float4*>(W2);
        float4 a0 = w1v[tid],       a1 = w1v[tid + 128];
        float4 a2 = w1v[tid + 256], a3 = w1v[tid + 384];
        float4 c0 = w2v[tid],       c1 = w2v[tid + 128];
        reinterpret_cast<float4*>(w1s)[tid]       = a0;
        reinterpret_cast<float4*>(w1s)[tid + 128] = a1;
        reinterpret_cast<float4*>(w1s)[tid + 256] = a2;
        reinterpret_cast<float4*>(w1s)[tid + 384] = a3;
        reinterpret_cast<float4*>(w2s)[tid]       = c0;
        reinterpret_cast<float4*>(w2s)[tid + 128] = c1;
    }
    if (tid < 32) {
        b2s[tid] = b2[tid];
        float acc = b1[tid];
        #pragma unroll
        for (int k = 0; k < D; k++)
            acc = fmaf(global_attr[k], W1[(64 + k) * 32 + tid], acc);
        gb[tid] = acc;
    }

    // ---- stage node_attr rows: 8 independent LDG.128/thread ----
    {
        const float4* nav = reinterpret_cast<const float4*>(node_attr) + (size_t)base * 8;
        float4 va[8];
        #pragma unroll
        for (int t = 0; t < 8; t++) {
            int idx = tid + 128 * t;
            if (full || (idx >> 3) < nvalid) va[t] = nav[idx];
            else va[t] = make_float4(0, 0, 0, 0);
        }
        #pragma unroll
        for (int t = 0; t < 8; t++) {
            int idx = tid + 128 * t;
            int n = idx >> 3, c = idx & 7;
            float* p = &xs[n * XSTR + 4 * c];
            p[0] = va[t].x; p[1] = va[t].y; p[2] = va[t].z; p[3] = va[t].w;
        }
    }
    __syncthreads();

    // ---- layer 1, node half: acc = gb + node @ W1[0:32] ----
    float acc[4][8];
    #pragma unroll
    for (int j = 0; j < 4; j++)
        #pragma unroll
        for (int m = 0; m < 8; m++) acc[j][m] = gb[cg * 8 + m];

    {
        const float* x0 = &xs[(4 * q + 0) * XSTR];
        const float* x1 = &xs[(4 * q + 1) * XSTR];
        const float* x2 = &xs[(4 * q + 2) * XSTR];
        const float* x3 = &xs[(4 * q + 3) * XSTR];
        #pragma unroll 4
        for (int k = 0; k < 32; k++) {
            float4 wa = *reinterpret_cast<const float4*>(&w1s[k * 32 + cg * 8]);
            float4 wb = *reinterpret_cast<const float4*>(&w1s[k * 32 + cg * 8 + 4]);
            float w[8] = {wa.x, wa.y, wa.z, wa.w, wb.x, wb.y, wb.z, wb.w};
            float xv[4] = {x0[k], x1[k], x2[k], x3[k]};
            #pragma unroll
            for (int j = 0; j < 4; j++)
                #pragma unroll
                for (int m = 0; m < 8; m++)
                    acc[j][m] = fmaf(xv[j], w[m], acc[j][m]);
        }
    }
    __syncthreads();   // done reading node attrs from xs

    // ---- gather: warp per node, ids preloaded, coalesced edge loads ----
    {
        const unsigned FULL = 0xffffffffu;
        const int wid  = tid >> 5;
        const int lane = tid & 31;
        const int g    = lane >> 3;   // edge sub-slot 0..3
        const int c    = lane & 7;    // float4 chunk 0..7
        const float4* ea4 = reinterpret_cast<const float4*>(edge_attr);

        for (int s = 0; s < 32; s++) {
            int n = wid * 32 + s;
            if (n >= nvalid) break;                 // warp-uniform
            int node = base + n;
            int count = g_cnt[node];
            if (count > CAP) count = CAP;
            const int* bk = g_bucket + (size_t)node * CAP;

            float4 a = make_float4(0.f, 0.f, 0.f, 0.f);
            for (int ch = 0; ch < count; ch += 32) {
                int cc = count - ch; if (cc > 32) cc = 32;
                int ids = (lane < cc) ? bk[ch + lane] : 0;   // 1 coalesced LDG
                for (int e = 0; e < cc; e += 4) {
                    int idx = e + g;
                    int id = __shfl_sync(FULL, ids, idx & 31);
                    if (idx < cc) {
                        float4 v = ea4[(size_t)id * 8 + c];  // 4x128B coalesced
                        a.x += v.x; a.y += v.y; a.z += v.z; a.w += v.w;
                    }
                }
            }
            // reduce the 4 edge sub-slots (lanes +16, +8)
            a.x += __shfl_down_sync(FULL, a.x, 16);
            a.y += __shfl_down_sync(FULL, a.y, 16);
            a.z += __shfl_down_sync(FULL, a.z, 16);
            a.w += __shfl_down_sync(FULL, a.w, 16);
            a.x += __shfl_down_sync(FULL, a.x, 8);
            a.y += __shfl_down_sync(FULL, a.y, 8);
            a.z += __shfl_down_sync(FULL, a.z, 8);
            a.w += __shfl_down_sync(FULL, a.w, 8);
            if (lane < 8) {
                float* p = &xs[n * XSTR + 4 * c];
                p[0] = a.x; p[1] = a.y; p[2] = a.z; p[3] = a.w;
            }
            if (lane == 0) g_cnt[node] = 0;   // reset for next call
        }
    }
    __syncthreads();

    // ---- layer 1, agg half: acc += agg @ W1[32:64] ----
    {
        const float* x0 = &xs[(4 * q + 0) * XSTR];
        const float* x1 = &xs[(4 * q + 1) * XSTR];
        const float* x2 = &xs[(4 * q + 2) * XSTR];
        const float* x3 = &xs[(4 * q + 3) * XSTR];
        #pragma unroll 4
        for (int k = 0; k < 32; k++) {
            float4 wa = *reinterpret_cast<const float4*>(&w1s[(32 + k) * 32 + cg * 8]);
            float4 wb = *reinterpret_cast<const float4*>(&w1s[(32 + k) * 32 + cg * 8 + 4]);
            float w[8] = {wa.x, wa.y, wa.z, wa.w, wb.x, wb.y, wb.z, wb.w};
            float xv[4] = {x0[k], x1[k], x2[k], x3[k]};
            #pragma unroll
            for (int j = 0; j < 4; j++)
                #pragma unroll
                for (int m = 0; m < 8; m++)
                    acc[j][m] = fmaf(xv[j], w[m], acc[j][m]);
        }
    }

    // ---- relu + h round-trip through xs ----
    __syncthreads();
    float* ht = xs;
    #pragma unroll
    for (int j = 0; j < 4; j++) {
        int n = 4 * q + j;
        #pragma unroll
        for (int m = 0; m < 8; m++)
            ht[n * XSTR + cg * 8 + m] = fmaxf(acc[j][m], 0.f);
    }
    __syncthreads();

    // ---- layer 2 ----
    float o[4][8];
    #pragma unroll
    for (int j = 0; j < 4; j++)
        #pragma unroll
        for (int m = 0; m < 8; m++) o[j][m] = b2s[cg * 8 + m];

    {
        const float* h0 = &ht[(4 * q + 0) * XSTR];
        const float* h1 = &ht[(4 * q + 1) * XSTR];
        const float* h2 = &ht[(4 * q + 2) * XSTR];
        const float* h3 = &ht[(4 * q + 3) * XSTR];
        #pragma unroll 4
        for (int i = 0; i < 32; i++) {
            float4 wa = *reinterpret_cast<const float4*>(&w2s[i * 32 + cg * 8]);
            float4 wb = *reinterpret_cast<const float4*>(&w2s[i * 32 + cg * 8 + 4]);
            float w[8] = {wa.x, wa.y, wa.z, wa.w, wb.x, wb.y, wb.z, wb.w};
            float hv[4] = {h0[i], h1[i], h2[i], h3[i]};
            #pragma unroll
            for (int j = 0; j < 4; j++)
                #pragma unroll
                for (int m = 0; m < 8; m++)
                    o[j][m] = fmaf(hv[j], w[m], o[j][m]);
        }
    }

    #pragma unroll
    for (int j = 0; j < 4; j++) {
        int n = 4 * q + j;
        if (n < nvalid) {
            float* dst = out + (size_t)(base + n) * OUT_FEAT + cg * 8;
            reinterpret_cast<float4*>(dst)[0] =
                make_float4(o[j][0], o[j][1], o[j][2], o[j][3]);
            reinterpret_cast<float4*>(dst)[1] =
                make_float4(o[j][4], o[j][5], o[j][6], o[j][7]);
        }
    }
}

// ---------------------------------------------------------------------------
// Launch.
// ---------------------------------------------------------------------------
extern "C" void kernel_launch(void* const* d_in, const int* in_sizes, int n_in,
                              void* d_out, int out_size) {
    const float* node_attr   = (const float*)d_in[0];
    const int*   edge_index  = (const int*)d_in[1];
    const float* edge_attr   = (const float*)d_in[2];
    const float* global_attr = (const float*)d_in[3];
    const float* W1          = (const float*)d_in[4];
    const float* b1          = (const float*)d_in[5];
    const float* W2          = (const float*)d_in[6];
    const float* b2          = (const float*)d_in[7];
    float*       out         = (float*)d_out;

    const int* receivers = edge_index + N_EDGES;

    // 1) bucket edge ids (g_cnt starts zero: load-init, reset by K2 each call)
    place_kernel<<<PLACE_BLOCKS, TPB>>>(receivers);

    // 2) gather + full MLP
    {
        size_t smem_bytes = SMEM_FLOATS * sizeof(float);
        cudaFuncSetAttribute(gather_mlp_kernel,
                             cudaFuncAttributeMaxDynamicSharedMemorySize,
                             (int)smem_bytes);
        gather_mlp_kernel<<<F_BLOCKS, TPB, smem_bytes>>>(
            node_attr, global_attr, edge_attr, W1, b1, W2, b2, out);
    }
    (void)in_sizes; (void)n_in; (void)out_size;
}

// round 9
// speedup vs baseline: 1.7502x; 1.7502x over previous
#include <cuda_runtime.h>
#include <cstdint>

#define N_NODES   100000
#define N_EDGES   1600000
#define D         32
#define OUT_FEAT  32

// Device-global scratch. g_agg zero-init at load; re-zeroed by final_kernel
// after consumption each call, so every launch sees a zeroed accumulator.
__device__ __align__(16) float g_agg[N_NODES * D];
__device__ __align__(16) float g_partial[N_NODES * D];   // node@W1[0:32] + gb

#define TPB  128
#define NB   128
#define XSTR 36    // row stride in floats: 16B-aligned, 9n mod 8 = n mod 8
                   // -> LDS.128 of rows {q+32j} conflict-free across q=0..7

#define S_LANES      (N_EDGES * 8)
#define S_PER_BLOCK  1024
#define S_BLOCKS     (S_LANES / S_PER_BLOCK)        // 12500
#define P_BLOCKS     ((N_NODES + NB - 1) / NB)      // 782

#define SMEM1_FLOATS (NB * XSTR + 32 * 32 + 32)              // fused partial
#define SMEM2_FLOATS (NB * XSTR + 32 * 32 + 32 * 32 + 32)    // final

// ---------------------------------------------------------------------------
// Fused kernel: blocks [0, P_BLOCKS) compute the scatter-independent term
// P = node@W1[0:32] + (b1 + global@W1[64:96]); the rest do the edge
// scatter-add (red.v4, LTS-RMW-bound — the partial work hides under it).
// ---------------------------------------------------------------------------
__global__ __launch_bounds__(TPB) void fused_partial_scatter(
    const float* __restrict__ edge_attr,
    const int* __restrict__ receivers,
    const float* __restrict__ node_attr,
    const float* __restrict__ global_attr,
    const float* __restrict__ W1,
    const float* __restrict__ b1)
{
    const int tid = threadIdx.x;

    if (blockIdx.x >= P_BLOCKS) {
        // ---------------- scatter path: 8 independent red.v4 per thread ----
        const int lane0 = (blockIdx.x - P_BLOCKS) * S_PER_BLOCK + tid;
        float4 v[8];
        int    r[8];
        #pragma unroll
        for (int t = 0; t < 8; t++) {
            int lane = lane0 + 128 * t;
            r[t] = receivers[lane >> 3];
            v[t] = reinterpret_cast<const float4*>(edge_attr)[lane];
        }
        #pragma unroll
        for (int t = 0; t < 8; t++) {
            int lane = lane0 + 128 * t;
            int c = lane & 7;
            if ((unsigned)r[t] < N_NODES) {
                float* dst = g_agg + (size_t)r[t] * D + c * 4;
                asm volatile("red.global.add.v4.f32 [%0], {%1, %2, %3, %4};"
                             :: "l"(dst), "f"(v[t].x), "f"(v[t].y),
                                "f"(v[t].z), "f"(v[t].w)
                             : "memory");
            }
        }
        return;
    }

    // ---------------- partial-MLP path: thread = cols 8cg, nodes q+32j -----
    extern __shared__ float smem[];
    float* xs  = smem;                  // [NB][XSTR]
    float* w1s = xs + NB * XSTR;        // [32][32]  W1 rows 0..31
    float* gb  = w1s + 32 * 32;         // [32]
    float4* xs4 = reinterpret_cast<float4*>(xs);   // row stride 9

    const int cg   = tid & 3;
    const int q    = tid >> 2;          // 0..31
    const int base = blockIdx.x * NB;
    const int nvalid = min(NB, N_NODES - base);
    const bool full  = (nvalid == NB);

    {
        const float4* w1v = reinterpret_cast<const float4*>(W1);
        float4 a0 = w1v[tid], a1 = w1v[tid + 128];
        reinterpret_cast<float4*>(w1s)[tid]       = a0;
        reinterpret_cast<float4*>(w1s)[tid + 128] = a1;
    }
    if (tid < 32) {
        float acc = b1[tid];
        #pragma unroll
        for (int k = 0; k < D; k++)
            acc = fmaf(global_attr[k], W1[(64 + k) * 32 + tid], acc);
        gb[tid] = acc;
    }
    {
        const float4* nav = reinterpret_cast<const float4*>(node_attr) + (size_t)base * 8;
        float4 va[8];
        #pragma unroll
        for (int t = 0; t < 8; t++) {
            int idx = tid + 128 * t;
            if (full || (idx >> 3) < nvalid) va[t] = nav[idx];
            else va[t] = make_float4(0, 0, 0, 0);
        }
        #pragma unroll
        for (int t = 0; t < 8; t++) {
            int idx = tid + 128 * t;
            xs4[(idx >> 3) * 9 + (idx & 7)] = va[t];
        }
    }
    __syncthreads();

    float acc[4][8];
    #pragma unroll
    for (int j = 0; j < 4; j++)
        #pragma unroll
        for (int m = 0; m < 8; m++) acc[j][m] = gb[cg * 8 + m];

    const float* xr[4] = { &xs[(q +  0) * XSTR], &xs[(q + 32) * XSTR],
                           &xs[(q + 64) * XSTR], &xs[(q + 96) * XSTR] };

    #pragma unroll
    for (int kb = 0; kb < 32; kb += 4) {
        float xv[4][4];
        #pragma unroll
        for (int j = 0; j < 4; j++)
            *reinterpret_cast<float4*>(xv[j]) =
                *reinterpret_cast<const float4*>(&xr[j][kb]);
        #pragma unroll
        for (int kk = 0; kk < 4; kk++) {
            int k = kb + kk;
            float4 wa = *reinterpret_cast<const float4*>(&w1s[k * 32 + cg * 8]);
            float4 wb = *reinterpret_cast<const float4*>(&w1s[k * 32 + cg * 8 + 4]);
            float w[8] = {wa.x, wa.y, wa.z, wa.w, wb.x, wb.y, wb.z, wb.w};
            #pragma unroll
            for (int j = 0; j < 4; j++)
                #pragma unroll
                for (int m = 0; m < 8; m++)
                    acc[j][m] = fmaf(xv[j][kk], w[m], acc[j][m]);
        }
    }

    #pragma unroll
    for (int j = 0; j < 4; j++) {
        int n = q + 32 * j;
        if (n < nvalid) {
            float* dst = g_partial + (size_t)(base + n) * D + cg * 8;
            reinterpret_cast<float4*>(dst)[0] =
                make_float4(acc[j][0], acc[j][1], acc[j][2], acc[j][3]);
            reinterpret_cast<float4*>(dst)[1] =
                make_float4(acc[j][4], acc[j][5], acc[j][6], acc[j][7]);
        }
    }
}

// ---------------------------------------------------------------------------
// Final kernel: out = relu(P + agg @ W1[32:64]) @ W2 + b2.
// Thread = cols 8cg..8cg+7, nodes {q, q+32, q+64, q+96}. LDS.128 everywhere.
// Re-zeroes its g_agg rows (replaces the memset node).
// ---------------------------------------------------------------------------
__global__ __launch_bounds__(TPB) void final_kernel(
    const float* __restrict__ W1,
    const float* __restrict__ W2, const float* __restrict__ b2,
    float* __restrict__ out)
{
    extern __shared__ float smem[];
    float* xs  = smem;                  // [NB][XSTR] agg; reused as ht
    float* w1s = xs + NB * XSTR;        // [32][32]  W1 rows 32..63
    float* w2s = w1s + 32 * 32;         // [32][32]
    float* b2s = w2s + 32 * 32;         // [32]
    float4* xs4 = reinterpret_cast<float4*>(xs);

    const int tid  = threadIdx.x;
    const int cg   = tid & 3;
    const int q    = tid >> 2;
    const int base = blockIdx.x * NB;
    const int nvalid = min(NB, N_NODES - base);
    const bool full  = (nvalid == NB);

    {
        const float4* w1v = reinterpret_cast<const float4*>(W1);
        const float4* w2v = reinterpret_cast<const float4*>(W2);
        float4 a0 = w1v[256 + tid], a1 = w1v[256 + tid + 128];
        float4 c0 = w2v[tid],       c1 = w2v[tid + 128];
        reinterpret_cast<float4*>(w1s)[tid]       = a0;
        reinterpret_cast<float4*>(w1s)[tid + 128] = a1;
        reinterpret_cast<float4*>(w2s)[tid]       = c0;
        reinterpret_cast<float4*>(w2s)[tid + 128] = c1;
    }
    if (tid < 32) b2s[tid] = b2[tid];

    // stage agg rows (L2-hot) + re-zero them for the next call
    {
        float4* agv = reinterpret_cast<float4*>(g_agg) + (size_t)base * 8;
        float4 vb[8];
        #pragma unroll
        for (int t = 0; t < 8; t++) {
            int idx = tid + 128 * t;
            if (full || (idx >> 3) < nvalid) vb[t] = agv[idx];
            else vb[t] = make_float4(0, 0, 0, 0);
        }
        #pragma unroll
        for (int t = 0; t < 8; t++) {
            int idx = tid + 128 * t;
            xs4[(idx >> 3) * 9 + (idx & 7)] = vb[t];
        }
        const float4 z = make_float4(0, 0, 0, 0);
        #pragma unroll
        for (int t = 0; t < 8; t++) {
            int idx = tid + 128 * t;
            if (full || (idx >> 3) < nvalid) agv[idx] = z;
        }
    }

    // load this thread's P tile (4 nodes x 8 cols)
    float acc[4][8];
    {
        const float4* pv = reinterpret_cast<const float4*>(g_partial) + (size_t)base * 8;
        #pragma unroll
        for (int j = 0; j < 4; j++) {
            int n = q + 32 * j;
            float4 pa, pb;
            if (full || n < nvalid) {
                pa = pv[n * 8 + cg * 2];
                pb = pv[n * 8 + cg * 2 + 1];
            } else { pa = make_float4(0,0,0,0); pb = pa; }
            acc[j][0] = pa.x; acc[j][1] = pa.y; acc[j][2] = pa.z; acc[j][3] = pa.w;
            acc[j][4] = pb.x; acc[j][5] = pb.y; acc[j][6] = pb.z; acc[j][7] = pb.w;
        }
    }
    __syncthreads();

    // layer 1 remainder: += agg @ W1[32:64]
    {
        const float* xr[4] = { &xs[(q +  0) * XSTR], &xs[(q + 32) * XSTR],
                               &xs[(q + 64) * XSTR], &xs[(q + 96) * XSTR] };
        #pragma unroll
        for (int kb = 0; kb < 32; kb += 4) {
            float xv[4][4];
            #pragma unroll
            for (int j = 0; j < 4; j++)
                *reinterpret_cast<float4*>(xv[j]) =
                    *reinterpret_cast<const float4*>(&xr[j][kb]);
            #pragma unroll
            for (int kk = 0; kk < 4; kk++) {
                int k = kb + kk;
                float4 wa = *reinterpret_cast<const float4*>(&w1s[k * 32 + cg * 8]);
                float4 wb = *reinterpret_cast<const float4*>(&w1s[k * 32 + cg * 8 + 4]);
                float w[8] = {wa.x, wa.y, wa.z, wa.w, wb.x, wb.y, wb.z, wb.w};
                #pragma unroll
                for (int j = 0; j < 4; j++)
                    #pragma unroll
                    for (int m = 0; m < 8; m++)
                        acc[j][m] = fmaf(xv[j][kk], w[m], acc[j][m]);
            }
        }
    }

    // relu + h round-trip through xs (STS.128)
    __syncthreads();
    #pragma unroll
    for (int j = 0; j < 4; j++) {
        int n = q + 32 * j;
        xs4[n * 9 + cg * 2] =
            make_float4(fmaxf(acc[j][0], 0.f), fmaxf(acc[j][1], 0.f),
                        fmaxf(acc[j][2], 0.f), fmaxf(acc[j][3], 0.f));
        xs4[n * 9 + cg * 2 + 1] =
            make_float4(fmaxf(acc[j][4], 0.f), fmaxf(acc[j][5], 0.f),
                        fmaxf(acc[j][6], 0.f), fmaxf(acc[j][7], 0.f));
    }
    __syncthreads();

    // layer 2
    float o[4][8];
    #pragma unroll
    for (int j = 0; j < 4; j++)
        #pragma unroll
        for (int m = 0; m < 8; m++) o[j][m] = b2s[cg * 8 + m];

    {
        const float* hr[4] = { &xs[(q +  0) * XSTR], &xs[(q + 32) * XSTR],
                               &xs[(q + 64) * XSTR], &xs[(q + 96) * XSTR] };
        #pragma unroll
        for (int ib = 0; ib < 32; ib += 4) {
            float hv[4][4];
            #pragma unroll
            for (int j = 0; j < 4; j++)
                *reinterpret_cast<float4*>(hv[j]) =
                    *reinterpret_cast<const float4*>(&hr[j][ib]);
            #pragma unroll
            for (int kk = 0; kk < 4; kk++) {
                int i = ib + kk;
                float4 wa = *reinterpret_cast<const float4*>(&w2s[i * 32 + cg * 8]);
                float4 wb = *reinterpret_cast<const float4*>(&w2s[i * 32 + cg * 8 + 4]);
                float w[8] = {wa.x, wa.y, wa.z, wa.w, wb.x, wb.y, wb.z, wb.w};
                #pragma unroll
                for (int j = 0; j < 4; j++)
                    #pragma unroll
                    for (int m = 0; m < 8; m++)
                        o[j][m] = fmaf(hv[j][kk], w[m], o[j][m]);
            }
        }
    }

    #pragma unroll
    for (int j = 0; j < 4; j++) {
        int n = q + 32 * j;
        if (n < nvalid) {
            float* dst = out + (size_t)(base + n) * OUT_FEAT + cg * 8;
            reinterpret_cast<float4*>(dst)[0] =
                make_float4(o[j][0], o[j][1], o[j][2], o[j][3]);
            reinterpret_cast<float4*>(dst)[1] =
                make_float4(o[j][4], o[j][5], o[j][6], o[j][7]);
        }
    }
}

// ---------------------------------------------------------------------------
// Launch.
// ---------------------------------------------------------------------------
extern "C" void kernel_launch(void* const* d_in, const int* in_sizes, int n_in,
                              void* d_out, int out_size) {
    const float* node_attr   = (const float*)d_in[0];
    const int*   edge_index  = (const int*)d_in[1];
    const float* edge_attr   = (const float*)d_in[2];
    const float* global_attr = (const float*)d_in[3];
    const float* W1          = (const float*)d_in[4];
    const float* b1          = (const float*)d_in[5];
    const float* W2          = (const float*)d_in[6];
    const float* b2          = (const float*)d_in[7];
    float*       out         = (float*)d_out;

    const int* receivers = edge_index + N_EDGES;

    // 1) fused partial MLP + scatter. g_agg is zero at entry (load-init /
    //    re-zeroed by final_kernel each call) — no memset node.
    {
        size_t smem1 = SMEM1_FLOATS * sizeof(float);
        cudaFuncSetAttribute(fused_partial_scatter,
                             cudaFuncAttributeMaxDynamicSharedMemorySize,
                             (int)smem1);
        fused_partial_scatter<<<P_BLOCKS + S_BLOCKS, TPB, smem1>>>(
            edge_attr, receivers, node_attr, global_attr, W1, b1);
    }

    // 2) final: relu(P + agg@W1b) @ W2 + b2; re-zeroes g_agg
    {
        size_t smem2 = SMEM2_FLOATS * sizeof(float);
        cudaFuncSetAttribute(final_kernel,
                             cudaFuncAttributeMaxDynamicSharedMemorySize,
                             (int)smem2);
        final_kernel<<<P_BLOCKS, TPB, smem2>>>(W1, W2, b2, out);
    }
    (void)in_sizes; (void)n_in; (void)out_size;
}

// round 10
// speedup vs baseline: 1.8199x; 1.0398x over previous
#include <cuda_runtime.h>
#include <cstdint>

#define N_NODES   100000
#define N_EDGES   1600000
#define D         32
#define OUT_FEAT  32

// Device-global scratch. g_agg is zero at load; final_kernel re-zeroes the
// rows it consumes every call, so each launch sees a zeroed accumulator.
__device__ __align__(16) float g_agg[N_NODES * D];
__device__ __align__(16) float g_partial[N_NODES * D];   // node@W1[0:32] + gb

#define TPB  128
#define NB   128
#define XSTR 33

#define P_BLOCKS     782                      // ceil(100000 / 128)
#define S_LANES      (N_EDGES * 8)            // 12.8M float4 lanes
#define S_PER_BLOCK  1024                     // 128 threads x 8 lanes
#define S_BLOCKS     (S_LANES / S_PER_BLOCK)  // 12500 exactly

// fused kernel smem (partial path): xs[128][33] + w1a[32][32] + gb[32]
#define SMEM1_FLOATS (NB * XSTR + 32 * 32 + 32)
// final kernel smem: xs/ht[128][33] + w1b[32][32] + w2[32][32] + b2[32]
#define SMEM2_FLOATS (NB * XSTR + 32 * 32 + 32 * 32 + 32)

// ---------------------------------------------------------------------------
// Kernel A (fused grid): blocks [0, P_BLOCKS) compute the scatter-independent
// partial MLP term P = node_attr @ W1[0:32] + (b1 + global @ W1[64:96]);
// blocks [P_BLOCKS, ...) do the edge scatter-add (red.v4, at the REDG
// issue floor ~1.29 cyc/lane). Partial work hides under the scatter.
// ---------------------------------------------------------------------------
__global__ __launch_bounds__(TPB) void fused_partial_scatter(
    const float* __restrict__ edge_attr,
    const int* __restrict__ receivers,
    const float* __restrict__ node_attr,
    const float* __restrict__ global_attr,
    const float* __restrict__ W1,
    const float* __restrict__ b1)
{
    const int tid = threadIdx.x;

    if (blockIdx.x >= P_BLOCKS) {
        // ---------------- scatter path: 8 independent lanes/thread ----------
        const int lane0 = (blockIdx.x - P_BLOCKS) * S_PER_BLOCK + tid;
        float4 v[8];
        int    r[8];
        #pragma unroll
        for (int t = 0; t < 8; t++) {
            int lane = lane0 + 128 * t;
            r[t] = receivers[lane >> 3];
            v[t] = reinterpret_cast<const float4*>(edge_attr)[lane];
        }
        #pragma unroll
        for (int t = 0; t < 8; t++) {
            int lane = lane0 + 128 * t;
            int c = lane & 7;
            if ((unsigned)r[t] < N_NODES) {
                float* dst = g_agg + (size_t)r[t] * D + c * 4;
                asm volatile("red.global.add.v4.f32 [%0], {%1, %2, %3, %4};"
                             :: "l"(dst), "f"(v[t].x), "f"(v[t].y),
                                "f"(v[t].z), "f"(v[t].w)
                             : "memory");
            }
        }
        return;
    }

    // ---------------- partial-MLP path ------------------------------------
    extern __shared__ float smem[];
    float* xs  = smem;                 // [NB][XSTR] node features
    float* w1s = xs + NB * XSTR;       // [32][32]  W1 rows 0..31
    float* gb  = w1s + 32 * 32;        // [32]

    const int cg   = tid & 3;
    const int q    = tid >> 2;
    const int base = blockIdx.x * NB;
    const int nvalid = min(NB, N_NODES - base);
    const bool full  = (nvalid == NB);

    // stage W1 rows 0..31 (1024 floats = 256 f4)
    {
        const float4* w1v = reinterpret_cast<const float4*>(W1);
        float4 a0 = w1v[tid], a1 = w1v[tid + 128];
        reinterpret_cast<float4*>(w1s)[tid]       = a0;
        reinterpret_cast<float4*>(w1s)[tid + 128] = a1;
    }
    // gb[j] = b1[j] + sum_k global[k] * W1[64+k][j]
    if (tid < 32) {
        float acc = b1[tid];
        #pragma unroll
        for (int k = 0; k < D; k++)
            acc = fmaf(global_attr[k], W1[(64 + k) * 32 + tid], acc);
        gb[tid] = acc;
    }
    // stage node rows: 1024 f4, 8 per thread, independent
    {
        const float4* nav = reinterpret_cast<const float4*>(node_attr) + (size_t)base * 8;
        float4 va[8];
        #pragma unroll
        for (int t = 0; t < 8; t++) {
            int idx = tid + 128 * t;
            if (full || (idx >> 3) < nvalid) va[t] = nav[idx];
            else va[t] = make_float4(0, 0, 0, 0);
        }
        #pragma unroll
        for (int t = 0; t < 8; t++) {
            int idx = tid + 128 * t;
            int n = idx >> 3, c = idx & 7;
            float* p = &xs[n * XSTR + 4 * c];
            p[0] = va[t].x; p[1] = va[t].y; p[2] = va[t].z; p[3] = va[t].w;
        }
    }
    __syncthreads();

    float acc[4][8];
    #pragma unroll
    for (int j = 0; j < 4; j++)
        #pragma unroll
        for (int m = 0; m < 8; m++) acc[j][m] = gb[cg * 8 + m];

    const float* x0 = &xs[(4 * q + 0) * XSTR];
    const float* x1 = &xs[(4 * q + 1) * XSTR];
    const float* x2 = &xs[(4 * q + 2) * XSTR];
    const float* x3 = &xs[(4 * q + 3) * XSTR];

    #pragma unroll 4
    for (int k = 0; k < 32; k++) {
        float4 wa = *reinterpret_cast<const float4*>(&w1s[k * 32 + cg * 8]);
        float4 wb = *reinterpret_cast<const float4*>(&w1s[k * 32 + cg * 8 + 4]);
        float w[8] = {wa.x, wa.y, wa.z, wa.w, wb.x, wb.y, wb.z, wb.w};
        float xv[4] = {x0[k], x1[k], x2[k], x3[k]};
        #pragma unroll
        for (int j = 0; j < 4; j++)
            #pragma unroll
            for (int m = 0; m < 8; m++)
                acc[j][m] = fmaf(xv[j], w[m], acc[j][m]);
    }

    // write P (no relu yet)
    #pragma unroll
    for (int j = 0; j < 4; j++) {
        int n = 4 * q + j;
        if (n < nvalid) {
            float* dst = g_partial + (size_t)(base + n) * D + cg * 8;
            reinterpret_cast<float4*>(dst)[0] =
                make_float4(acc[j][0], acc[j][1], acc[j][2], acc[j][3]);
            reinterpret_cast<float4*>(dst)[1] =
                make_float4(acc[j][4], acc[j][5], acc[j][6], acc[j][7]);
        }
    }
}

// ---------------------------------------------------------------------------
// Kernel B: final = relu(P + agg @ W1[32:64]) @ W2 + b2.
// Identical to the proven 19.1us version, plus: re-zeroes the g_agg rows it
// just read (replaces the serial memset node; stores hidden under the k-loop).
// ---------------------------------------------------------------------------
__global__ __launch_bounds__(TPB) void final_kernel(
    const float* __restrict__ W1,
    const float* __restrict__ W2, const float* __restrict__ b2,
    float* __restrict__ out)
{
    extern __shared__ float smem[];
    float* xs  = smem;                 // [NB][XSTR] agg features; reused as ht
    float* w1s = xs + NB * XSTR;       // [32][32]  W1 rows 32..63
    float* w2s = w1s + 32 * 32;        // [32][32]
    float* b2s = w2s + 32 * 32;        // [32]

    const int tid  = threadIdx.x;
    const int cg   = tid & 3;
    const int q    = tid >> 2;
    const int base = blockIdx.x * NB;
    const int nvalid = min(NB, N_NODES - base);
    const bool full  = (nvalid == NB);

    // stage W1 rows 32..63 (f4 offset 256) and W2
    {
        const float4* w1v = reinterpret_cast<const float4*>(W1);
        const float4* w2v = reinterpret_cast<const float4*>(W2);
        float4 a0 = w1v[256 + tid], a1 = w1v[256 + tid + 128];
        float4 c0 = w2v[tid],       c1 = w2v[tid + 128];
        reinterpret_cast<float4*>(w1s)[tid]       = a0;
        reinterpret_cast<float4*>(w1s)[tid + 128] = a1;
        reinterpret_cast<float4*>(w2s)[tid]       = c0;
        reinterpret_cast<float4*>(w2s)[tid + 128] = c1;
    }
    if (tid < 32) b2s[tid] = b2[tid];

    // stage agg rows (L2-hot), 8 f4/thread; then re-zero them (same thread
    // read them — no race; restores the zero invariant for the next call)
    {
        float4* agv = reinterpret_cast<float4*>(g_agg) + (size_t)base * 8;
        float4 vb[8];
        #pragma unroll
        for (int t = 0; t < 8; t++) {
            int idx = tid + 128 * t;
            if (full || (idx >> 3) < nvalid) vb[t] = agv[idx];
            else vb[t] = make_float4(0, 0, 0, 0);
        }
        #pragma unroll
        for (int t = 0; t < 8; t++) {
            int idx = tid + 128 * t;
            int n = idx >> 3, c = idx & 7;
            float* p = &xs[n * XSTR + 4 * c];
            p[0] = vb[t].x; p[1] = vb[t].y; p[2] = vb[t].z; p[3] = vb[t].w;
        }
        const float4 z = make_float4(0, 0, 0, 0);
        #pragma unroll
        for (int t = 0; t < 8; t++) {
            int idx = tid + 128 * t;
            if (full || (idx >> 3) < nvalid) agv[idx] = z;
        }
    }

    // load this thread's P tile (4 nodes x 8 cols)
    float acc[4][8];
    {
        const float4* pv = reinterpret_cast<const float4*>(g_partial) + (size_t)base * 8;
        #pragma unroll
        for (int j = 0; j < 4; j++) {
            int n = 4 * q + j;
            float4 pa, pb;
            if (full || n < nvalid) {
                pa = pv[n * 8 + cg * 2];
                pb = pv[n * 8 + cg * 2 + 1];
            } else { pa = make_float4(0,0,0,0); pb = pa; }
            acc[j][0] = pa.x; acc[j][1] = pa.y; acc[j][2] = pa.z; acc[j][3] = pa.w;
            acc[j][4] = pb.x; acc[j][5] = pb.y; acc[j][6] = pb.z; acc[j][7] = pb.w;
        }
    }
    __syncthreads();

    // layer 1 remainder: += agg @ W1[32:64]
    const float* x0 = &xs[(4 * q + 0) * XSTR];
    const float* x1 = &xs[(4 * q + 1) * XSTR];
    const float* x2 = &xs[(4 * q + 2) * XSTR];
    const float* x3 = &xs[(4 * q + 3) * XSTR];

    #pragma unroll 4
    for (int k = 0; k < 32; k++) {
        float4 wa = *reinterpret_cast<const float4*>(&w1s[k * 32 + cg * 8]);
        float4 wb = *reinterpret_cast<const float4*>(&w1s[k * 32 + cg * 8 + 4]);
        float w[8] = {wa.x, wa.y, wa.z, wa.w, wb.x, wb.y, wb.z, wb.w};
        float xv[4] = {x0[k], x1[k], x2[k], x3[k]};
        #pragma unroll
        for (int j = 0; j < 4; j++)
            #pragma unroll
            for (int m = 0; m < 8; m++)
                acc[j][m] = fmaf(xv[j], w[m], acc[j][m]);
    }

    // relu + round-trip h through smem (reuse xs region)
    __syncthreads();
    float* ht = xs;   // [NB][XSTR]
    #pragma unroll
    for (int j = 0; j < 4; j++) {
        int n = 4 * q + j;
        #pragma unroll
        for (int m = 0; m < 8; m++)
            ht[n * XSTR + cg * 8 + m] = fmaxf(acc[j][m], 0.f);
    }
    __syncthreads();

    // layer 2
    float o[4][8];
    #pragma unroll
    for (int j = 0; j < 4; j++)
        #pragma unroll
        for (int m = 0; m < 8; m++) o[j][m] = b2s[cg * 8 + m];

    const float* h0 = &ht[(4 * q + 0) * XSTR];
    const float* h1 = &ht[(4 * q + 1) * XSTR];
    const float* h2 = &ht[(4 * q + 2) * XSTR];
    const float* h3 = &ht[(4 * q + 3) * XSTR];

    #pragma unroll 4
    for (int i = 0; i < 32; i++) {
        float4 wa = *reinterpret_cast<const float4*>(&w2s[i * 32 + cg * 8]);
        float4 wb = *reinterpret_cast<const float4*>(&w2s[i * 32 + cg * 8 + 4]);
        float w[8] = {wa.x, wa.y, wa.z, wa.w, wb.x, wb.y, wb.z, wb.w};
        float hv[4] = {h0[i], h1[i], h2[i], h3[i]};
        #pragma unroll
        for (int j = 0; j < 4; j++)
            #pragma unroll
            for (int m = 0; m < 8; m++)
                o[j][m] = fmaf(hv[j], w[m], o[j][m]);
    }

    #pragma unroll
    for (int j = 0; j < 4; j++) {
        int n = 4 * q + j;
        if (n < nvalid) {
            float* dst = out + (size_t)(base + n) * OUT_FEAT + cg * 8;
            reinterpret_cast<float4*>(dst)[0] =
                make_float4(o[j][0], o[j][1], o[j][2], o[j][3]);
            reinterpret_cast<float4*>(dst)[1] =
                make_float4(o[j][4], o[j][5], o[j][6], o[j][7]);
        }
    }
}

// ---------------------------------------------------------------------------
// Launch.
// ---------------------------------------------------------------------------
extern "C" void kernel_launch(void* const* d_in, const int* in_sizes, int n_in,
                              void* d_out, int out_size) {
    const float* node_attr   = (const float*)d_in[0];
    const int*   edge_index  = (const int*)d_in[1];
    const float* edge_attr   = (const float*)d_in[2];
    const float* global_attr = (const float*)d_in[3];
    const float* W1          = (const float*)d_in[4];
    const float* b1          = (const float*)d_in[5];
    const float* W2          = (const float*)d_in[6];
    const float* b2          = (const float*)d_in[7];
    float*       out         = (float*)d_out;

    const int* receivers = edge_index + N_EDGES;

    // 1) fused partial-MLP + scatter (partial blocks first — proven layout).
    //    g_agg is zero at entry: load-time init, re-zeroed by final_kernel.
    {
        size_t smem1 = SMEM1_FLOATS * sizeof(float);
        cudaFuncSetAttribute(fused_partial_scatter,
                             cudaFuncAttributeMaxDynamicSharedMemorySize,
                             (int)smem1);
        fused_partial_scatter<<<P_BLOCKS + S_BLOCKS, TPB, smem1>>>(
            edge_attr, receivers, node_attr, global_attr, W1, b1);
    }

    // 2) final: relu(P + agg@W1b) @ W2 + b2; re-zeroes g_agg
    {
        size_t smem2 = SMEM2_FLOATS * sizeof(float);
        cudaFuncSetAttribute(final_kernel,
                             cudaFuncAttributeMaxDynamicSharedMemorySize,
                             (int)smem2);
        final_kernel<<<P_BLOCKS, TPB, smem2>>>(W1, W2, b2, out);
    }
    (void)in_sizes; (void)n_in; (void)out_size;
}

// round 11
// speedup vs baseline: 1.9307x; 1.0609x over previous
#include <cuda_runtime.h>
#include <cstdint>

#define N_NODES   100000
#define N_EDGES   1600000
#define D         32
#define OUT_FEAT  32

// L2-resident scratch (device globals: no allocation allowed in kernel_launch)
__device__ __align__(16) float g_agg[N_NODES * D];       // segment_sum result
__device__ __align__(16) float g_partial[N_NODES * D];   // node@W1[0:32] + gb

#define TPB  128
#define NB   128
#define XSTR 33

#define P_BLOCKS     782                      // ceil(100000 / 128)
#define S_LANES      (N_EDGES * 8)            // 12.8M float4 lanes
#define S_PER_BLOCK  1024                     // 128 threads x 8 lanes
#define S_BLOCKS     (S_LANES / S_PER_BLOCK)  // 12500 exactly
#define T_BLOCKS     (S_BLOCKS + P_BLOCKS)    // 13282

// fused kernel smem (partial path): xs[128][33] + w1a[32][32] + gb[32]
#define SMEM1_FLOATS (NB * XSTR + 32 * 32 + 32)
// final kernel smem: xs/ht[128][33] + w1b[32][32] + w2[32][32] + b2[32]
#define SMEM2_FLOATS (NB * XSTR + 32 * 32 + 32 * 32 + 32)

// ---------------------------------------------------------------------------
// Fused kernel with INTERLEAVED roles: partial-MLP blocks are spread evenly
// through the grid (Bresenham: ~1 per 17 blocks) so their FMA/LDS work
// co-resides with the LSU-bound scatter instead of forming a serial tail.
// ---------------------------------------------------------------------------
__global__ __launch_bounds__(TPB) void fused_scatter_partial(
    const float* __restrict__ edge_attr,
    const int* __restrict__ receivers,
    const float* __restrict__ node_attr,
    const float* __restrict__ global_attr,
    const float* __restrict__ W1,
    const float* __restrict__ b1)
{
    const int tid = threadIdx.x;

    // Bresenham role split: block bid is "partial" iff
    // floor((bid+1)*P/T) > floor(bid*P/T); exactly P_BLOCKS such bids.
    const long long a = (long long)blockIdx.x * P_BLOCKS;
    const int p_before = (int)(a / T_BLOCKS);
    const int p_after  = (int)((a + P_BLOCKS) / T_BLOCKS);
    const bool is_partial = (p_after > p_before);

    if (!is_partial) {
        // ---------------- scatter path: 8 independent lanes/thread ----------
        const int s_idx = blockIdx.x - p_before;          // 0..S_BLOCKS-1
        const int lane0 = s_idx * S_PER_BLOCK + tid;
        float4 v[8];
        int    r[8];
        #pragma unroll
        for (int t = 0; t < 8; t++) {
            int lane = lane0 + 128 * t;
            r[t] = receivers[lane >> 3];
            v[t] = reinterpret_cast<const float4*>(edge_attr)[lane];
        }
        #pragma unroll
        for (int t = 0; t < 8; t++) {
            int lane = lane0 + 128 * t;
            int c = lane & 7;
            if ((unsigned)r[t] < N_NODES) {
                float* dst = g_agg + (size_t)r[t] * D + c * 4;
                asm volatile("red.global.add.v4.f32 [%0], {%1, %2, %3, %4};"
                             :: "l"(dst), "f"(v[t].x), "f"(v[t].y),
                                "f"(v[t].z), "f"(v[t].w)
                             : "memory");
            }
        }
        return;
    }

    // ---------------- partial-MLP path (4 nodes x 8 cols per thread) -------
    extern __shared__ float smem[];
    float* xs  = smem;                 // [NB][XSTR] node features
    float* w1s = xs + NB * XSTR;       // [32][32]  W1 rows 0..31
    float* gb  = w1s + 32 * 32;        // [32]

    const int cg   = tid & 3;
    const int q    = tid >> 2;
    const int base = p_before * NB;    // partial index = p_before
    const int nvalid = min(NB, N_NODES - base);
    const bool full  = (nvalid == NB);

    // stage W1 rows 0..31 (1024 floats = 256 f4)
    {
        const float4* w1v = reinterpret_cast<const float4*>(W1);
        float4 a0 = w1v[tid], a1 = w1v[tid + 128];
        reinterpret_cast<float4*>(w1s)[tid]       = a0;
        reinterpret_cast<float4*>(w1s)[tid + 128] = a1;
    }
    // gb[j] = b1[j] + sum_k global[k] * W1[64+k][j]
    if (tid < 32) {
        float acc = b1[tid];
        #pragma unroll
        for (int k = 0; k < D; k++)
            acc = fmaf(global_attr[k], W1[(64 + k) * 32 + tid], acc);
        gb[tid] = acc;
    }
    // stage node rows: 1024 f4, 8 per thread, independent
    {
        const float4* nav = reinterpret_cast<const float4*>(node_attr) + (size_t)base * 8;
        float4 va[8];
        #pragma unroll
        for (int t = 0; t < 8; t++) {
            int idx = tid + 128 * t;
            if (full || (idx >> 3) < nvalid) va[t] = nav[idx];
            else va[t] = make_float4(0, 0, 0, 0);
        }
        #pragma unroll
        for (int t = 0; t < 8; t++) {
            int idx = tid + 128 * t;
            int n = idx >> 3, c = idx & 7;
            float* p = &xs[n * XSTR + 4 * c];
            p[0] = va[t].x; p[1] = va[t].y; p[2] = va[t].z; p[3] = va[t].w;
        }
    }
    __syncthreads();

    float acc[4][8];
    #pragma unroll
    for (int j = 0; j < 4; j++)
        #pragma unroll
        for (int m = 0; m < 8; m++) acc[j][m] = gb[cg * 8 + m];

    const float* x0 = &xs[(4 * q + 0) * XSTR];
    const float* x1 = &xs[(4 * q + 1) * XSTR];
    const float* x2 = &xs[(4 * q + 2) * XSTR];
    const float* x3 = &xs[(4 * q + 3) * XSTR];

    #pragma unroll 4
    for (int k = 0; k < 32; k++) {
        float4 wa = *reinterpret_cast<const float4*>(&w1s[k * 32 + cg * 8]);
        float4 wb = *reinterpret_cast<const float4*>(&w1s[k * 32 + cg * 8 + 4]);
        float w[8] = {wa.x, wa.y, wa.z, wa.w, wb.x, wb.y, wb.z, wb.w};
        float xv[4] = {x0[k], x1[k], x2[k], x3[k]};
        #pragma unroll
        for (int j = 0; j < 4; j++)
            #pragma unroll
            for (int m = 0; m < 8; m++)
                acc[j][m] = fmaf(xv[j], w[m], acc[j][m]);
    }

    // write P (no relu yet)
    #pragma unroll
    for (int j = 0; j < 4; j++) {
        int n = 4 * q + j;
        if (n < nvalid) {
            float* dst = g_partial + (size_t)(base + n) * D + cg * 8;
            reinterpret_cast<float4*>(dst)[0] =
                make_float4(acc[j][0], acc[j][1], acc[j][2], acc[j][3]);
            reinterpret_cast<float4*>(dst)[1] =
                make_float4(acc[j][4], acc[j][5], acc[j][6], acc[j][7]);
        }
    }
}

// ---------------------------------------------------------------------------
// Final kernel: out = relu(P + agg @ W1[32:64]) @ W2 + b2  (proven 19.1us).
// ---------------------------------------------------------------------------
__global__ __launch_bounds__(TPB) void final_kernel(
    const float* __restrict__ W1,
    const float* __restrict__ W2, const float* __restrict__ b2,
    float* __restrict__ out)
{
    extern __shared__ float smem[];
    float* xs  = smem;                 // [NB][XSTR] agg features; reused as ht
    float* w1s = xs + NB * XSTR;       // [32][32]  W1 rows 32..63
    float* w2s = w1s + 32 * 32;        // [32][32]
    float* b2s = w2s + 32 * 32;        // [32]

    const int tid  = threadIdx.x;
    const int cg   = tid & 3;
    const int q    = tid >> 2;
    const int base = blockIdx.x * NB;
    const int nvalid = min(NB, N_NODES - base);
    const bool full  = (nvalid == NB);

    // stage W1 rows 32..63 (f4 offset 256) and W2
    {
        const float4* w1v = reinterpret_cast<const float4*>(W1);
        const float4* w2v = reinterpret_cast<const float4*>(W2);
        float4 a0 = w1v[256 + tid], a1 = w1v[256 + tid + 128];
        float4 c0 = w2v[tid],       c1 = w2v[tid + 128];
        reinterpret_cast<float4*>(w1s)[tid]       = a0;
        reinterpret_cast<float4*>(w1s)[tid + 128] = a1;
        reinterpret_cast<float4*>(w2s)[tid]       = c0;
        reinterpret_cast<float4*>(w2s)[tid + 128] = c1;
    }
    if (tid < 32) b2s[tid] = b2[tid];

    // stage agg rows (L2-hot), 8 f4/thread
    {
        const float4* agv = reinterpret_cast<const float4*>(g_agg) + (size_t)base * 8;
        float4 vb[8];
        #pragma unroll
        for (int t = 0; t < 8; t++) {
            int idx = tid + 128 * t;
            if (full || (idx >> 3) < nvalid) vb[t] = agv[idx];
            else vb[t] = make_float4(0, 0, 0, 0);
        }
        #pragma unroll
        for (int t = 0; t < 8; t++) {
            int idx = tid + 128 * t;
            int n = idx >> 3, c = idx & 7;
            float* p = &xs[n * XSTR + 4 * c];
            p[0] = vb[t].x; p[1] = vb[t].y; p[2] = vb[t].z; p[3] = vb[t].w;
        }
    }

    // load this thread's P tile (4 nodes x 8 cols)
    float acc[4][8];
    {
        const float4* pv = reinterpret_cast<const float4*>(g_partial) + (size_t)base * 8;
        #pragma unroll
        for (int j = 0; j < 4; j++) {
            int n = 4 * q + j;
            float4 pa, pb;
            if (full || n < nvalid) {
                pa = pv[n * 8 + cg * 2];
                pb = pv[n * 8 + cg * 2 + 1];
            } else { pa = make_float4(0,0,0,0); pb = pa; }
            acc[j][0] = pa.x; acc[j][1] = pa.y; acc[j][2] = pa.z; acc[j][3] = pa.w;
            acc[j][4] = pb.x; acc[j][5] = pb.y; acc[j][6] = pb.z; acc[j][7] = pb.w;
        }
    }
    __syncthreads();

    // layer 1 remainder: += agg @ W1[32:64]
    const float* x0 = &xs[(4 * q + 0) * XSTR];
    const float* x1 = &xs[(4 * q + 1) * XSTR];
    const float* x2 = &xs[(4 * q + 2) * XSTR];
    const float* x3 = &xs[(4 * q + 3) * XSTR];

    #pragma unroll 4
    for (int k = 0; k < 32; k++) {
        float4 wa = *reinterpret_cast<const float4*>(&w1s[k * 32 + cg * 8]);
        float4 wb = *reinterpret_cast<const float4*>(&w1s[k * 32 + cg * 8 + 4]);
        float w[8] = {wa.x, wa.y, wa.z, wa.w, wb.x, wb.y, wb.z, wb.w};
        float xv[4] = {x0[k], x1[k], x2[k], x3[k]};
        #pragma unroll
        for (int j = 0; j < 4; j++)
            #pragma unroll
            for (int m = 0; m < 8; m++)
                acc[j][m] = fmaf(xv[j], w[m], acc[j][m]);
    }

    // relu + round-trip h through smem (reuse xs region)
    __syncthreads();
    float* ht = xs;   // [NB][XSTR]
    #pragma unroll
    for (int j = 0; j < 4; j++) {
        int n = 4 * q + j;
        #pragma unroll
        for (int m = 0; m < 8; m++)
            ht[n * XSTR + cg * 8 + m] = fmaxf(acc[j][m], 0.f);
    }
    __syncthreads();

    // layer 2
    float o[4][8];
    #pragma unroll
    for (int j = 0; j < 4; j++)
        #pragma unroll
        for (int m = 0; m < 8; m++) o[j][m] = b2s[cg * 8 + m];

    const float* h0 = &ht[(4 * q + 0) * XSTR];
    const float* h1 = &ht[(4 * q + 1) * XSTR];
    const float* h2 = &ht[(4 * q + 2) * XSTR];
    const float* h3 = &ht[(4 * q + 3) * XSTR];

    #pragma unroll 4
    for (int i = 0; i < 32; i++) {
        float4 wa = *reinterpret_cast<const float4*>(&w2s[i * 32 + cg * 8]);
        float4 wb = *reinterpret_cast<const float4*>(&w2s[i * 32 + cg * 8 + 4]);
        float w[8] = {wa.x, wa.y, wa.z, wa.w, wb.x, wb.y, wb.z, wb.w};
        float hv[4] = {h0[i], h1[i], h2[i], h3[i]};
        #pragma unroll
        for (int j = 0; j < 4; j++)
            #pragma unroll
            for (int m = 0; m < 8; m++)
                o[j][m] = fmaf(hv[j], w[m], o[j][m]);
    }

    #pragma unroll
    for (int j = 0; j < 4; j++) {
        int n = 4 * q + j;
        if (n < nvalid) {
            float* dst = out + (size_t)(base + n) * OUT_FEAT + cg * 8;
            reinterpret_cast<float4*>(dst)[0] =
                make_float4(o[j][0], o[j][1], o[j][2], o[j][3]);
            reinterpret_cast<float4*>(dst)[1] =
                make_float4(o[j][4], o[j][5], o[j][6], o[j][7]);
        }
    }
}

// ---------------------------------------------------------------------------
// Launch.
// ---------------------------------------------------------------------------
extern "C" void kernel_launch(void* const* d_in, const int* in_sizes, int n_in,
                              void* d_out, int out_size) {
    const float* node_attr   = (const float*)d_in[0];
    const int*   edge_index  = (const int*)d_in[1];
    const float* edge_attr   = (const float*)d_in[2];
    const float* global_attr = (const float*)d_in[3];
    const float* W1          = (const float*)d_in[4];
    const float* b1          = (const float*)d_in[5];
    const float* W2          = (const float*)d_in[6];
    const float* b2          = (const float*)d_in[7];
    float*       out         = (float*)d_out;

    const int* receivers = edge_index + N_EDGES;

    // 1) zero accumulator (graph memset node — proven cheaper than in-kernel)
    void* agg_ptr = nullptr;
    cudaGetSymbolAddress(&agg_ptr, g_agg);
    cudaMemsetAsync(agg_ptr, 0, (size_t)N_NODES * D * sizeof(float));

    // 2) fused scatter + interleaved partial MLP
    {
        size_t smem1 = SMEM1_FLOATS * sizeof(float);
        cudaFuncSetAttribute(fused_scatter_partial,
                             cudaFuncAttributeMaxDynamicSharedMemorySize,
                             (int)smem1);
        fused_scatter_partial<<<T_BLOCKS, TPB, smem1>>>(
            edge_attr, receivers, node_attr, global_attr, W1, b1);
    }

    // 3) final: relu(P + agg@W1b) @ W2 + b2
    {
        size_t smem2 = SMEM2_FLOATS * sizeof(float);
        cudaFuncSetAttribute(final_kernel,
                             cudaFuncAttributeMaxDynamicSharedMemorySize,
                             (int)smem2);
        final_kernel<<<P_BLOCKS, TPB, smem2>>>(W1, W2, b2, out);
    }
    (void)in_sizes; (void)n_in; (void)out_size;
}

// round 12
// speedup vs baseline: 2.0191x; 1.0458x over previous
#include <cuda_runtime.h>
#include <cstdint>

#define N_NODES   100000
#define N_EDGES   1600000
#define D         32
#define OUT_FEAT  32

__device__ __align__(16) float g_agg[N_NODES * D];       // segment_sum result
__device__ __align__(16) float g_partial[N_NODES * D];   // node@W1[0:32] + gb

#define TPB  128
#define NB   128
#define XSTR 33

#define P_BLOCKS     782                      // ceil(100000 / 128)
#define S_LANES      (N_EDGES * 8)            // 12.8M float4 lanes
#define S_PER_BLOCK  1024                     // 128 threads x 8 lanes
#define S_BLOCKS     (S_LANES / S_PER_BLOCK)  // 12500 exactly
#define T_BLOCKS     (S_BLOCKS + P_BLOCKS)    // 13282

#define SMEM1_FLOATS (NB * XSTR + 32 * 32 + 32)
#define SMEM2_FLOATS (NB * XSTR + 32 * 32 + 32 * 32 + 32)

#define PDL_TRIGGER() asm volatile("griddepcontrol.launch_dependents;" ::: "memory")
#define PDL_WAIT()    asm volatile("griddepcontrol.wait;" ::: "memory")

// ---------------------------------------------------------------------------
// Kernel 0: zero g_agg (replaces the memset node; triggers PDL immediately so
// the fused kernel's input-only prologue overlaps with the zeroing stores).
// ---------------------------------------------------------------------------
#define Z_BLOCKS 1600   // 1600 * 128 * 4 f4 = 819200 f4 = 3.2M floats
__global__ __launch_bounds__(TPB) void zero_kernel() {
    PDL_TRIGGER();
    float4* p = reinterpret_cast<float4*>(g_agg);
    const int i0 = blockIdx.x * (TPB * 4) + threadIdx.x;
    const float4 z = make_float4(0.f, 0.f, 0.f, 0.f);
    #pragma unroll
    for (int t = 0; t < 4; t++) p[i0 + TPB * t] = z;
}

// ---------------------------------------------------------------------------
// Kernel 1 (fused, PDL secondary of zero / primary of final):
// scatter blocks prefetch inputs PRE-wait, then wait for zero, then red.
// partial blocks touch nothing the zero kernel writes -> no wait at all.
// Bresenham-interleaved roles (proven round 11).
// ---------------------------------------------------------------------------
__global__ __launch_bounds__(TPB) void fused_scatter_partial(
    const float* __restrict__ edge_attr,
    const int* __restrict__ receivers,
    const float* __restrict__ node_attr,
    const float* __restrict__ global_attr,
    const float* __restrict__ W1,
    const float* __restrict__ b1)
{
    PDL_TRIGGER();   // let final_kernel's weight staging start early
    const int tid = threadIdx.x;

    const long long a = (long long)blockIdx.x * P_BLOCKS;
    const int p_before = (int)(a / T_BLOCKS);
    const int p_after  = (int)((a + P_BLOCKS) / T_BLOCKS);
    const bool is_partial = (p_after > p_before);

    if (!is_partial) {
        // -------- scatter: prefetch (inputs only) pre-wait ------------------
        const int s_idx = blockIdx.x - p_before;
        const int lane0 = s_idx * S_PER_BLOCK + tid;
        float4 v[8];
        int    r[8];
        #pragma unroll
        for (int t = 0; t < 8; t++) {
            int lane = lane0 + 128 * t;
            r[t] = receivers[lane >> 3];
            v[t] = reinterpret_cast<const float4*>(edge_attr)[lane];
        }
        PDL_WAIT();   // g_agg fully zeroed beyond this point
        #pragma unroll
        for (int t = 0; t < 8; t++) {
            int lane = lane0 + 128 * t;
            int c = lane & 7;
            if ((unsigned)r[t] < N_NODES) {
                float* dst = g_agg + (size_t)r[t] * D + c * 4;
                asm volatile("red.global.add.v4.f32 [%0], {%1, %2, %3, %4};"
                             :: "l"(dst), "f"(v[t].x), "f"(v[t].y),
                                "f"(v[t].z), "f"(v[t].w)
                             : "memory");
            }
        }
        return;
    }

    // -------- partial-MLP path: independent of g_agg, no wait needed --------
    extern __shared__ float smem[];
    float* xs  = smem;                 // [NB][XSTR]
    float* w1s = xs + NB * XSTR;       // [32][32]  W1 rows 0..31
    float* gb  = w1s + 32 * 32;        // [32]

    const int cg   = tid & 3;
    const int q    = tid >> 2;
    const int base = p_before * NB;
    const int nvalid = min(NB, N_NODES - base);
    const bool full  = (nvalid == NB);

    {
        const float4* w1v = reinterpret_cast<const float4*>(W1);
        float4 a0 = w1v[tid], a1 = w1v[tid + 128];
        reinterpret_cast<float4*>(w1s)[tid]       = a0;
        reinterpret_cast<float4*>(w1s)[tid + 128] = a1;
    }
    if (tid < 32) {
        float acc = b1[tid];
        #pragma unroll
        for (int k = 0; k < D; k++)
            acc = fmaf(global_attr[k], W1[(64 + k) * 32 + tid], acc);
        gb[tid] = acc;
    }
    {
        const float4* nav = reinterpret_cast<const float4*>(node_attr) + (size_t)base * 8;
        float4 va[8];
        #pragma unroll
        for (int t = 0; t < 8; t++) {
            int idx = tid + 128 * t;
            if (full || (idx >> 3) < nvalid) va[t] = nav[idx];
            else va[t] = make_float4(0, 0, 0, 0);
        }
        #pragma unroll
        for (int t = 0; t < 8; t++) {
            int idx = tid + 128 * t;
            int n = idx >> 3, c = idx & 7;
            float* p = &xs[n * XSTR + 4 * c];
            p[0] = va[t].x; p[1] = va[t].y; p[2] = va[t].z; p[3] = va[t].w;
        }
    }
    __syncthreads();

    float acc[4][8];
    #pragma unroll
    for (int j = 0; j < 4; j++)
        #pragma unroll
        for (int m = 0; m < 8; m++) acc[j][m] = gb[cg * 8 + m];

    const float* x0 = &xs[(4 * q + 0) * XSTR];
    const float* x1 = &xs[(4 * q + 1) * XSTR];
    const float* x2 = &xs[(4 * q + 2) * XSTR];
    const float* x3 = &xs[(4 * q + 3) * XSTR];

    #pragma unroll 4
    for (int k = 0; k < 32; k++) {
        float4 wa = *reinterpret_cast<const float4*>(&w1s[k * 32 + cg * 8]);
        float4 wb = *reinterpret_cast<const float4*>(&w1s[k * 32 + cg * 8 + 4]);
        float w[8] = {wa.x, wa.y, wa.z, wa.w, wb.x, wb.y, wb.z, wb.w};
        float xv[4] = {x0[k], x1[k], x2[k], x3[k]};
        #pragma unroll
        for (int j = 0; j < 4; j++)
            #pragma unroll
            for (int m = 0; m < 8; m++)
                acc[j][m] = fmaf(xv[j], w[m], acc[j][m]);
    }

    #pragma unroll
    for (int j = 0; j < 4; j++) {
        int n = 4 * q + j;
        if (n < nvalid) {
            float* dst = g_partial + (size_t)(base + n) * D + cg * 8;
            reinterpret_cast<float4*>(dst)[0] =
                make_float4(acc[j][0], acc[j][1], acc[j][2], acc[j][3]);
            reinterpret_cast<float4*>(dst)[1] =
                make_float4(acc[j][4], acc[j][5], acc[j][6], acc[j][7]);
        }
    }
}

// ---------------------------------------------------------------------------
// Kernel 2 (PDL secondary): stage weights pre-wait (inputs only), then wait
// for fused, then agg/P reads + MLP. Hot loops identical to proven 19.1us.
// ---------------------------------------------------------------------------
__global__ __launch_bounds__(TPB) void final_kernel(
    const float* __restrict__ W1,
    const float* __restrict__ W2, const float* __restrict__ b2,
    float* __restrict__ out)
{
    extern __shared__ float smem[];
    float* xs  = smem;                 // [NB][XSTR] agg; reused as ht
    float* w1s = xs + NB * XSTR;       // [32][32]  W1 rows 32..63
    float* w2s = w1s + 32 * 32;        // [32][32]
    float* b2s = w2s + 32 * 32;        // [32]

    const int tid  = threadIdx.x;
    const int cg   = tid & 3;
    const int q    = tid >> 2;
    const int base = blockIdx.x * NB;
    const int nvalid = min(NB, N_NODES - base);
    const bool full  = (nvalid == NB);

    // -------- PRE-WAIT: weights/biases are pure inputs ----------------------
    {
        const float4* w1v = reinterpret_cast<const float4*>(W1);
        const float4* w2v = reinterpret_cast<const float4*>(W2);
        float4 a0 = w1v[256 + tid], a1 = w1v[256 + tid + 128];
        float4 c0 = w2v[tid],       c1 = w2v[tid + 128];
        reinterpret_cast<float4*>(w1s)[tid]       = a0;
        reinterpret_cast<float4*>(w1s)[tid + 128] = a1;
        reinterpret_cast<float4*>(w2s)[tid]       = c0;
        reinterpret_cast<float4*>(w2s)[tid + 128] = c1;
    }
    if (tid < 32) b2s[tid] = b2[tid];

    PDL_WAIT();   // g_agg and g_partial complete beyond this point

    // stage agg rows (L2-hot), 8 f4/thread
    {
        const float4* agv = reinterpret_cast<const float4*>(g_agg) + (size_t)base * 8;
        float4 vb[8];
        #pragma unroll
        for (int t = 0; t < 8; t++) {
            int idx = tid + 128 * t;
            if (full || (idx >> 3) < nvalid) vb[t] = agv[idx];
            else vb[t] = make_float4(0, 0, 0, 0);
        }
        #pragma unroll
        for (int t = 0; t < 8; t++) {
            int idx = tid + 128 * t;
            int n = idx >> 3, c = idx & 7;
            float* p = &xs[n * XSTR + 4 * c];
            p[0] = vb[t].x; p[1] = vb[t].y; p[2] = vb[t].z; p[3] = vb[t].w;
        }
    }

    // load this thread's P tile (4 nodes x 8 cols)
    float acc[4][8];
    {
        const float4* pv = reinterpret_cast<const float4*>(g_partial) + (size_t)base * 8;
        #pragma unroll
        for (int j = 0; j < 4; j++) {
            int n = 4 * q + j;
            float4 pa, pb;
            if (full || n < nvalid) {
                pa = pv[n * 8 + cg * 2];
                pb = pv[n * 8 + cg * 2 + 1];
            } else { pa = make_float4(0,0,0,0); pb = pa; }
            acc[j][0] = pa.x; acc[j][1] = pa.y; acc[j][2] = pa.z; acc[j][3] = pa.w;
            acc[j][4] = pb.x; acc[j][5] = pb.y; acc[j][6] = pb.z; acc[j][7] = pb.w;
        }
    }
    __syncthreads();

    // layer 1 remainder: += agg @ W1[32:64]
    const float* x0 = &xs[(4 * q + 0) * XSTR];
    const float* x1 = &xs[(4 * q + 1) * XSTR];
    const float* x2 = &xs[(4 * q + 2) * XSTR];
    const float* x3 = &xs[(4 * q + 3) * XSTR];

    #pragma unroll 4
    for (int k = 0; k < 32; k++) {
        float4 wa = *reinterpret_cast<const float4*>(&w1s[k * 32 + cg * 8]);
        float4 wb = *reinterpret_cast<const float4*>(&w1s[k * 32 + cg * 8 + 4]);
        float w[8] = {wa.x, wa.y, wa.z, wa.w, wb.x, wb.y, wb.z, wb.w};
        float xv[4] = {x0[k], x1[k], x2[k], x3[k]};
        #pragma unroll
        for (int j = 0; j < 4; j++)
            #pragma unroll
            for (int m = 0; m < 8; m++)
                acc[j][m] = fmaf(xv[j], w[m], acc[j][m]);
    }

    __syncthreads();
    float* ht = xs;
    #pragma unroll
    for (int j = 0; j < 4; j++) {
        int n = 4 * q + j;
        #pragma unroll
        for (int m = 0; m < 8; m++)
            ht[n * XSTR + cg * 8 + m] = fmaxf(acc[j][m], 0.f);
    }
    __syncthreads();

    float o[4][8];
    #pragma unroll
    for (int j = 0; j < 4; j++)
        #pragma unroll
        for (int m = 0; m < 8; m++) o[j][m] = b2s[cg * 8 + m];

    const float* h0 = &ht[(4 * q + 0) * XSTR];
    const float* h1 = &ht[(4 * q + 1) * XSTR];
    const float* h2 = &ht[(4 * q + 2) * XSTR];
    const float* h3 = &ht[(4 * q + 3) * XSTR];

    #pragma unroll 4
    for (int i = 0; i < 32; i++) {
        float4 wa = *reinterpret_cast<const float4*>(&w2s[i * 32 + cg * 8]);
        float4 wb = *reinterpret_cast<const float4*>(&w2s[i * 32 + cg * 8 + 4]);
        float w[8] = {wa.x, wa.y, wa.z, wa.w, wb.x, wb.y, wb.z, wb.w};
        float hv[4] = {h0[i], h1[i], h2[i], h3[i]};
        #pragma unroll
        for (int j = 0; j < 4; j++)
            #pragma unroll
            for (int m = 0; m < 8; m++)
                o[j][m] = fmaf(hv[j], w[m], o[j][m]);
    }

    #pragma unroll
    for (int j = 0; j < 4; j++) {
        int n = 4 * q + j;
        if (n < nvalid) {
            float* dst = out + (size_t)(base + n) * OUT_FEAT + cg * 8;
            reinterpret_cast<float4*>(dst)[0] =
                make_float4(o[j][0], o[j][1], o[j][2], o[j][3]);
            reinterpret_cast<float4*>(dst)[1] =
                make_float4(o[j][4], o[j][5], o[j][6], o[j][7]);
        }
    }
}

// ---------------------------------------------------------------------------
// Launch: zero ->(PDL) fused ->(PDL) final, all on the capture stream.
// ---------------------------------------------------------------------------
static void launch_pdl(const void* func, dim3 grid, dim3 block, size_t smem,
                       void** args) {
    cudaLaunchConfig_t cfg = {};
    cfg.gridDim = grid;
    cfg.blockDim = block;
    cfg.dynamicSmemBytes = smem;
    cudaLaunchAttribute attr[1];
    attr[0].id = cudaLaunchAttributeProgrammaticStreamSerialization;
    attr[0].val.programmaticStreamSerializationAllowed = 1;
    cfg.attrs = attr;
    cfg.numAttrs = 1;
    cudaLaunchKernelExC(&cfg, func, args);
}

extern "C" void kernel_launch(void* const* d_in, const int* in_sizes, int n_in,
                              void* d_out, int out_size) {
    const float* node_attr   = (const float*)d_in[0];
    const int*   edge_index  = (const int*)d_in[1];
    const float* edge_attr   = (const float*)d_in[2];
    const float* global_attr = (const float*)d_in[3];
    const float* W1          = (const float*)d_in[4];
    const float* b1          = (const float*)d_in[5];
    const float* W2          = (const float*)d_in[6];
    const float* b2          = (const float*)d_in[7];
    float*       out         = (float*)d_out;

    const int* receivers = edge_index + N_EDGES;

    // 1) zero g_agg (kernel, triggers PDL at start)
    zero_kernel<<<Z_BLOCKS, TPB>>>();

    // 2) fused scatter + interleaved partial MLP (PDL: prefetch pre-wait)
    {
        void* args[] = { (void*)&edge_attr, (void*)&receivers,
                         (void*)&node_attr, (void*)&global_attr,
                         (void*)&W1, (void*)&b1 };
        launch_pdl((const void*)fused_scatter_partial,
                   dim3(T_BLOCKS), dim3(TPB),
                   SMEM1_FLOATS * sizeof(float), args);
    }

    // 3) final (PDL: weight staging pre-wait)
    {
        void* args[] = { (void*)&W1, (void*)&W2, (void*)&b2, (void*)&out };
        launch_pdl((const void*)final_kernel,
                   dim3(P_BLOCKS), dim3(TPB),
                   SMEM2_FLOATS * sizeof(float), args);
    }
    (void)in_sizes; (void)n_in; (void)out_size;
}

// round 13
// speedup vs baseline: 2.2324x; 1.1056x over previous
#include <cuda_runtime.h>
#include <cstdint>

#define N_NODES   100000
#define N_EDGES   1600000
#define D         32
#define OUT_FEAT  32

__device__ __align__(16) float g_agg[N_NODES * D];       // segment_sum result
__device__ __align__(16) float g_partial[N_NODES * D];   // node@W1[0:32] + gb

#define TPB  128
#define NB   128
#define XSTR 33

#define P_BLOCKS     782                      // ceil(100000 / 128)
#define EPB          128                      // edges per scatter block
#define S_BLOCKS     (N_EDGES / EPB)          // 12500 exactly
#define T_BLOCKS     (S_BLOCKS + P_BLOCKS)    // 13282

// dyn smem: scatter path uses EPB*32 floats (16KB) staged edges;
// partial path uses xs[128][33] + w1a[32][32] + gb[32] (17.1KB). Take max.
#define SMEM1_FLOATS (NB * XSTR + 32 * 32 + 32)
#define SMEM2_FLOATS (NB * XSTR + 32 * 32 + 32 * 32 + 32)

#define PDL_TRIGGER() asm volatile("griddepcontrol.launch_dependents;" ::: "memory")
#define PDL_WAIT()    asm volatile("griddepcontrol.wait;" ::: "memory")

// ---------------------------------------------------------------------------
// Kernel 0: zero g_agg (PDL primary; fused prefetch overlaps the zeroing).
// ---------------------------------------------------------------------------
#define Z_BLOCKS 1600
__global__ __launch_bounds__(TPB) void zero_kernel() {
    PDL_TRIGGER();
    float4* p = reinterpret_cast<float4*>(g_agg);
    const int i0 = blockIdx.x * (TPB * 4) + threadIdx.x;
    const float4 z = make_float4(0.f, 0.f, 0.f, 0.f);
    #pragma unroll
    for (int t = 0; t < 4; t++) p[i0 + TPB * t] = z;
}

// ---------------------------------------------------------------------------
// Kernel 1 (fused): scatter blocks stage 128 edges in smem and issue ONE
// cp.reduce.async.bulk (128B) per edge — 8x fewer SM-issue ops than red.v4,
// RMW done by the TMA/L2 path. Partial-MLP blocks Bresenham-interleaved.
// ---------------------------------------------------------------------------
__global__ __launch_bounds__(TPB) void fused_scatter_partial(
    const float* __restrict__ edge_attr,
    const int* __restrict__ receivers,
    const float* __restrict__ node_attr,
    const float* __restrict__ global_attr,
    const float* __restrict__ W1,
    const float* __restrict__ b1)
{
    PDL_TRIGGER();
    const int tid = threadIdx.x;

    const long long a = (long long)blockIdx.x * P_BLOCKS;
    const int p_before = (int)(a / T_BLOCKS);
    const int p_after  = (int)((a + P_BLOCKS) / T_BLOCKS);
    const bool is_partial = (p_after > p_before);

    extern __shared__ float smem[];

    if (!is_partial) {
        // -------- scatter via TMA bulk-reduce --------------------------------
        float4* b4 = reinterpret_cast<float4*>(smem);   // 1024 f4 = 128 edges
        const int s_idx = blockIdx.x - p_before;        // 0..S_BLOCKS-1
        const int e0 = s_idx * EPB;

        // coalesced prefetch: 8 independent LDG.128 per thread (inputs only)
        const float4* src = reinterpret_cast<const float4*>(edge_attr) + (size_t)e0 * 8;
        float4 v[8];
        #pragma unroll
        for (int t = 0; t < 8; t++) v[t] = src[tid + 128 * t];
        const int r = receivers[e0 + tid];              // this thread's edge

        // stage edges contiguously: edge e occupies smem bytes [e*128, e*128+128)
        #pragma unroll
        for (int t = 0; t < 8; t++) b4[tid + 128 * t] = v[t];

        // make generic-proxy STS visible to the async (TMA) proxy
        asm volatile("fence.proxy.async.shared::cta;" ::: "memory");
        __syncthreads();

        PDL_WAIT();   // g_agg fully zeroed beyond this point

        uint32_t sb;
        asm("{ .reg .u64 t; cvta.to.shared.u64 t, %1; cvt.u32.u64 %0, t; }"
            : "=r"(sb) : "l"(smem));

        if ((unsigned)r < N_NODES) {
            float* dst = g_agg + (size_t)r * D;         // 128B-aligned
            asm volatile(
                "cp.reduce.async.bulk.global.shared::cta.bulk_group.add.f32 "
                "[%0], [%1], 128;"
                :: "l"(dst), "r"(sb + (unsigned)tid * 128)
                : "memory");
        }
        asm volatile("cp.async.bulk.commit_group;" ::: "memory");
        // full completion: reduce writes visible before grid completes (PDL)
        asm volatile("cp.async.bulk.wait_group 0;" ::: "memory");
        return;
    }

    // -------- partial-MLP path (unchanged, proven) ---------------------------
    float* xs  = smem;                 // [NB][XSTR]
    float* w1s = xs + NB * XSTR;       // [32][32]  W1 rows 0..31
    float* gb  = w1s + 32 * 32;        // [32]

    const int cg   = tid & 3;
    const int q    = tid >> 2;
    const int base = p_before * NB;
    const int nvalid = min(NB, N_NODES - base);
    const bool full  = (nvalid == NB);

    {
        const float4* w1v = reinterpret_cast<const float4*>(W1);
        float4 a0 = w1v[tid], a1 = w1v[tid + 128];
        reinterpret_cast<float4*>(w1s)[tid]       = a0;
        reinterpret_cast<float4*>(w1s)[tid + 128] = a1;
    }
    if (tid < 32) {
        float acc = b1[tid];
        #pragma unroll
        for (int k = 0; k < D; k++)
            acc = fmaf(global_attr[k], W1[(64 + k) * 32 + tid], acc);
        gb[tid] = acc;
    }
    {
        const float4* nav = reinterpret_cast<const float4*>(node_attr) + (size_t)base * 8;
        float4 va[8];
        #pragma unroll
        for (int t = 0; t < 8; t++) {
            int idx = tid + 128 * t;
            if (full || (idx >> 3) < nvalid) va[t] = nav[idx];
            else va[t] = make_float4(0, 0, 0, 0);
        }
        #pragma unroll
        for (int t = 0; t < 8; t++) {
            int idx = tid + 128 * t;
            int n = idx >> 3, c = idx & 7;
            float* p = &xs[n * XSTR + 4 * c];
            p[0] = va[t].x; p[1] = va[t].y; p[2] = va[t].z; p[3] = va[t].w;
        }
    }
    __syncthreads();

    float acc[4][8];
    #pragma unroll
    for (int j = 0; j < 4; j++)
        #pragma unroll
        for (int m = 0; m < 8; m++) acc[j][m] = gb[cg * 8 + m];

    const float* x0 = &xs[(4 * q + 0) * XSTR];
    const float* x1 = &xs[(4 * q + 1) * XSTR];
    const float* x2 = &xs[(4 * q + 2) * XSTR];
    const float* x3 = &xs[(4 * q + 3) * XSTR];

    #pragma unroll 4
    for (int k = 0; k < 32; k++) {
        float4 wa = *reinterpret_cast<const float4*>(&w1s[k * 32 + cg * 8]);
        float4 wb = *reinterpret_cast<const float4*>(&w1s[k * 32 + cg * 8 + 4]);
        float w[8] = {wa.x, wa.y, wa.z, wa.w, wb.x, wb.y, wb.z, wb.w};
        float xv[4] = {x0[k], x1[k], x2[k], x3[k]};
        #pragma unroll
        for (int j = 0; j < 4; j++)
            #pragma unroll
            for (int m = 0; m < 8; m++)
                acc[j][m] = fmaf(xv[j], w[m], acc[j][m]);
    }

    #pragma unroll
    for (int j = 0; j < 4; j++) {
        int n = 4 * q + j;
        if (n < nvalid) {
            float* dst = g_partial + (size_t)(base + n) * D + cg * 8;
            reinterpret_cast<float4*>(dst)[0] =
                make_float4(acc[j][0], acc[j][1], acc[j][2], acc[j][3]);
            reinterpret_cast<float4*>(dst)[1] =
                make_float4(acc[j][4], acc[j][5], acc[j][6], acc[j][7]);
        }
    }
}

// ---------------------------------------------------------------------------
// Kernel 2 (PDL secondary): weights staged pre-wait; then agg/P + MLP.
// ---------------------------------------------------------------------------
__global__ __launch_bounds__(TPB) void final_kernel(
    const float* __restrict__ W1,
    const float* __restrict__ W2, const float* __restrict__ b2,
    float* __restrict__ out)
{
    extern __shared__ float smem[];
    float* xs  = smem;                 // [NB][XSTR] agg; reused as ht
    float* w1s = xs + NB * XSTR;       // [32][32]  W1 rows 32..63
    float* w2s = w1s + 32 * 32;        // [32][32]
    float* b2s = w2s + 32 * 32;        // [32]

    const int tid  = threadIdx.x;
    const int cg   = tid & 3;
    const int q    = tid >> 2;
    const int base = blockIdx.x * NB;
    const int nvalid = min(NB, N_NODES - base);
    const bool full  = (nvalid == NB);

    {
        const float4* w1v = reinterpret_cast<const float4*>(W1);
        const float4* w2v = reinterpret_cast<const float4*>(W2);
        float4 a0 = w1v[256 + tid], a1 = w1v[256 + tid + 128];
        float4 c0 = w2v[tid],       c1 = w2v[tid + 128];
        reinterpret_cast<float4*>(w1s)[tid]       = a0;
        reinterpret_cast<float4*>(w1s)[tid + 128] = a1;
        reinterpret_cast<float4*>(w2s)[tid]       = c0;
        reinterpret_cast<float4*>(w2s)[tid + 128] = c1;
    }
    if (tid < 32) b2s[tid] = b2[tid];

    PDL_WAIT();   // g_agg and g_partial complete beyond this point

    {
        const float4* agv = reinterpret_cast<const float4*>(g_agg) + (size_t)base * 8;
        float4 vb[8];
        #pragma unroll
        for (int t = 0; t < 8; t++) {
            int idx = tid + 128 * t;
            if (full || (idx >> 3) < nvalid) vb[t] = agv[idx];
            else vb[t] = make_float4(0, 0, 0, 0);
        }
        #pragma unroll
        for (int t = 0; t < 8; t++) {
            int idx = tid + 128 * t;
            int n = idx >> 3, c = idx & 7;
            float* p = &xs[n * XSTR + 4 * c];
            p[0] = vb[t].x; p[1] = vb[t].y; p[2] = vb[t].z; p[3] = vb[t].w;
        }
    }

    float acc[4][8];
    {
        const float4* pv = reinterpret_cast<const float4*>(g_partial) + (size_t)base * 8;
        #pragma unroll
        for (int j = 0; j < 4; j++) {
            int n = 4 * q + j;
            float4 pa, pb;
            if (full || n < nvalid) {
                pa = pv[n * 8 + cg * 2];
                pb = pv[n * 8 + cg * 2 + 1];
            } else { pa = make_float4(0,0,0,0); pb = pa; }
            acc[j][0] = pa.x; acc[j][1] = pa.y; acc[j][2] = pa.z; acc[j][3] = pa.w;
            acc[j][4] = pb.x; acc[j][5] = pb.y; acc[j][6] = pb.z; acc[j][7] = pb.w;
        }
    }
    __syncthreads();

    const float* x0 = &xs[(4 * q + 0) * XSTR];
    const float* x1 = &xs[(4 * q + 1) * XSTR];
    const float* x2 = &xs[(4 * q + 2) * XSTR];
    const float* x3 = &xs[(4 * q + 3) * XSTR];

    #pragma unroll 4
    for (int k = 0; k < 32; k++) {
        float4 wa = *reinterpret_cast<const float4*>(&w1s[k * 32 + cg * 8]);
        float4 wb = *reinterpret_cast<const float4*>(&w1s[k * 32 + cg * 8 + 4]);
        float w[8] = {wa.x, wa.y, wa.z, wa.w, wb.x, wb.y, wb.z, wb.w};
        float xv[4] = {x0[k], x1[k], x2[k], x3[k]};
        #pragma unroll
        for (int j = 0; j < 4; j++)
            #pragma unroll
            for (int m = 0; m < 8; m++)
                acc[j][m] = fmaf(xv[j], w[m], acc[j][m]);
    }

    __syncthreads();
    float* ht = xs;
    #pragma unroll
    for (int j = 0; j < 4; j++) {
        int n = 4 * q + j;
        #pragma unroll
        for (int m = 0; m < 8; m++)
            ht[n * XSTR + cg * 8 + m] = fmaxf(acc[j][m], 0.f);
    }
    __syncthreads();

    float o[4][8];
    #pragma unroll
    for (int j = 0; j < 4; j++)
        #pragma unroll
        for (int m = 0; m < 8; m++) o[j][m] = b2s[cg * 8 + m];

    const float* h0 = &ht[(4 * q + 0) * XSTR];
    const float* h1 = &ht[(4 * q + 1) * XSTR];
    const float* h2 = &ht[(4 * q + 2) * XSTR];
    const float* h3 = &ht[(4 * q + 3) * XSTR];

    #pragma unroll 4
    for (int i = 0; i < 32; i++) {
        float4 wa = *reinterpret_cast<const float4*>(&w2s[i * 32 + cg * 8]);
        float4 wb = *reinterpret_cast<const float4*>(&w2s[i * 32 + cg * 8 + 4]);
        float w[8] = {wa.x, wa.y, wa.z, wa.w, wb.x, wb.y, wb.z, wb.w};
        float hv[4] = {h0[i], h1[i], h2[i], h3[i]};
        #pragma unroll
        for (int j = 0; j < 4; j++)
            #pragma unroll
            for (int m = 0; m < 8; m++)
                o[j][m] = fmaf(hv[j], w[m], o[j][m]);
    }

    #pragma unroll
    for (int j = 0; j < 4; j++) {
        int n = 4 * q + j;
        if (n < nvalid) {
            float* dst = out + (size_t)(base + n) * OUT_FEAT + cg * 8;
            reinterpret_cast<float4*>(dst)[0] =
                make_float4(o[j][0], o[j][1], o[j][2], o[j][3]);
            reinterpret_cast<float4*>(dst)[1] =
                make_float4(o[j][4], o[j][5], o[j][6], o[j][7]);
        }
    }
}

// ---------------------------------------------------------------------------
// Launch: zero ->(PDL) fused ->(PDL) final.
// ---------------------------------------------------------------------------
static void launch_pdl(const void* func, dim3 grid, dim3 block, size_t smem,
                       void** args) {
    cudaLaunchConfig_t cfg = {};
    cfg.gridDim = grid;
    cfg.blockDim = block;
    cfg.dynamicSmemBytes = smem;
    cudaLaunchAttribute attr[1];
    attr[0].id = cudaLaunchAttributeProgrammaticStreamSerialization;
    attr[0].val.programmaticStreamSerializationAllowed = 1;
    cfg.attrs = attr;
    cfg.numAttrs = 1;
    cudaLaunchKernelExC(&cfg, func, args);
}

extern "C" void kernel_launch(void* const* d_in, const int* in_sizes, int n_in,
                              void* d_out, int out_size) {
    const float* node_attr   = (const float*)d_in[0];
    const int*   edge_index  = (const int*)d_in[1];
    const float* edge_attr   = (const float*)d_in[2];
    const float* global_attr = (const float*)d_in[3];
    const float* W1          = (const float*)d_in[4];
    const float* b1          = (const float*)d_in[5];
    const float* W2          = (const float*)d_in[6];
    const float* b2          = (const float*)d_in[7];
    float*       out         = (float*)d_out;

    const int* receivers = edge_index + N_EDGES;

    zero_kernel<<<Z_BLOCKS, TPB>>>();

    {
        void* args[] = { (void*)&edge_attr, (void*)&receivers,
                         (void*)&node_attr, (void*)&global_attr,
                         (void*)&W1, (void*)&b1 };
        launch_pdl((const void*)fused_scatter_partial,
                   dim3(T_BLOCKS), dim3(TPB),
                   SMEM1_FLOATS * sizeof(float), args);
    }

    {
        void* args[] = { (void*)&W1, (void*)&W2, (void*)&b2, (void*)&out };
        launch_pdl((const void*)final_kernel,
                   dim3(P_BLOCKS), dim3(TPB),
                   SMEM2_FLOATS * sizeof(float), args);
    }
    (void)in_sizes; (void)n_in; (void)out_size;
}